// round 13
// baseline (speedup 1.0000x reference)
#include <cuda_runtime.h>
#include <cuda_fp16.h>
#include <cuda_bf16.h>
#include <cstdint>

#define Bsz 4
#define Cch 4
#define Tlen 4096
#define Hdim 256
#define INNER 512
#define Sdim 64
#define Lnum 3
#define Vsz 1024
#define Mrows (Bsz*Tlen)   // 16384

// ---------------- scratch (allocation-free rule: __device__ globals) ----------------
__device__ float  g_emb  [Bsz*Tlen*Hdim];     // fp32 residual chain
__device__ float  g_featA[Bsz*Tlen*Hdim];
__device__ float  g_featB[Bsz*Tlen*Hdim];
__device__ __half g_emb_h [Bsz*Tlen*Hdim];    // fp16 GEMM-A shadows
__device__ __half g_feat_h[Bsz*Tlen*Hdim];
__device__ __half g_u    [Bsz*Tlen*Sdim];
__device__ __half g_hs   [Bsz*Tlen*Sdim];
__device__ __half g_xp   [Bsz*Tlen*2*INNER];
__device__ __half g_xc   [Bsz*Tlen*INNER];
__device__ __half g_z    [Bsz*Tlen*INNER];
__device__ __half g_pat  [Bsz*Tlen*Hdim];
__device__ __half g_fused[Bsz*Tlen*Hdim];
// fp16 weight copies
__device__ __half g_inw_h [Lnum*2*INNER*Hdim];
__device__ __half g_bpw_h [Lnum*Sdim*INNER];
__device__ __half g_cpw_h [Lnum*INNER*Sdim];
__device__ __half g_outw_h[Lnum*Hdim*INNER];
__device__ __half g_fusw_h[Hdim*2*Hdim];
__device__ __half g_headw_h[Cch*Vsz*Hdim];
__device__ __half g_patw_h[4*3*64*Hdim];

__device__ __forceinline__ float siluf(float x) {
    return x * (1.0f / (1.0f + __expf(-x)));
}

__device__ __forceinline__ uint32_t smem_u32(const void* p) {
    uint32_t a;
    asm("{ .reg .u64 t; cvta.to.shared.u64 t, %1; cvt.u32.u64 %0, t; }" : "=r"(a) : "l"(p));
    return a;
}

__device__ __forceinline__ void mma16(float c[4], const uint32_t a[4], const uint32_t b[2]) {
    asm volatile(
        "mma.sync.aligned.m16n8k16.row.col.f32.f16.f16.f32 "
        "{%0,%1,%2,%3},{%4,%5,%6,%7},{%8,%9},{%0,%1,%2,%3};\n"
        : "+f"(c[0]), "+f"(c[1]), "+f"(c[2]), "+f"(c[3])
        : "r"(a[0]), "r"(a[1]), "r"(a[2]), "r"(a[3]), "r"(b[0]), "r"(b[1]));
}

__device__ __forceinline__ void ldsm4(uint32_t r[4], uint32_t addr) {
    asm volatile("ldmatrix.sync.aligned.m8n8.x4.shared.b16 {%0,%1,%2,%3}, [%4];"
        : "=r"(r[0]), "=r"(r[1]), "=r"(r[2]), "=r"(r[3]) : "r"(addr));
}

// ---------------- all weight fp32->fp16 conversions in one launch ----------------
#define CS0 (Lnum*2*INNER*Hdim)          // 786432
#define CS1 (Lnum*Sdim*INNER)            // 98304
#define CS2 (Lnum*INNER*Sdim)            // 98304
#define CS3 (Lnum*Hdim*INNER)            // 393216
#define CS4 (Hdim*2*Hdim)                // 131072
#define CS5 (Cch*Vsz*Hdim)               // 1048576
#define CTOT (CS0+CS1+CS2+CS3+CS4+CS5)
__global__ void convert_all(const float* __restrict__ w0, __half* __restrict__ o0,
                            const float* __restrict__ w1, __half* __restrict__ o1,
                            const float* __restrict__ w2, __half* __restrict__ o2,
                            const float* __restrict__ w3, __half* __restrict__ o3,
                            const float* __restrict__ w4, __half* __restrict__ o4,
                            const float* __restrict__ w5, __half* __restrict__ o5)
{
    int idx = blockIdx.x*256 + threadIdx.x;
    if (idx >= CTOT) return;
    if (idx < CS0) { o0[idx] = __float2half(w0[idx]); return; }
    idx -= CS0;
    if (idx < CS1) { o1[idx] = __float2half(w1[idx]); return; }
    idx -= CS1;
    if (idx < CS2) { o2[idx] = __float2half(w2[idx]); return; }
    idx -= CS2;
    if (idx < CS3) { o3[idx] = __float2half(w3[idx]); return; }
    idx -= CS3;
    if (idx < CS4) { o4[idx] = __float2half(w4[idx]); return; }
    idx -= CS4;
    o5[idx] = __float2half(w5[idx]);
}

// ---------------- embedding: mean_c tok_emb + pos + text (fp32 + fp16 shadow) ----------------
__global__ void embed_kernel(const int* __restrict__ tok, const float* __restrict__ text,
                             const float* __restrict__ tok_emb, const float* __restrict__ pos_emb,
                             const int* __restrict__ pos_off, float* __restrict__ out,
                             __half* __restrict__ outh)
{
    int bt = blockIdx.x;
    int b = bt >> 12, t = bt & 4095;
    int h = threadIdx.x;           // 256
    int off = pos_off[0];
    float s = 0.f;
#pragma unroll
    for (int c = 0; c < Cch; c++) {
        int v = tok[(b*Cch + c)*Tlen + t];
        s += tok_emb[((size_t)(c*Vsz + v))*Hdim + h];
    }
    float r = 0.25f*s + pos_emb[(size_t)(off + t)*Hdim + h] + text[b*Hdim + h];
    out[(size_t)bt*Hdim + h] = r;
    outh[(size_t)bt*Hdim + h] = __float2half(r);
}

// ---------------- causal depthwise conv (k=4) + bias + silu, half2 x 2 channels ----------------
#define CTT 16
__global__ void conv_silu_kernel(const __half* __restrict__ xp, const float* __restrict__ w4,
                                 const float* __restrict__ cb, __half* __restrict__ xc)
{
    int i2 = threadIdx.x;          // 0..255 -> channels 2*i2, 2*i2+1
    int bt0 = blockIdx.x * CTT;
    int b = bt0 >> 12;
    int t0 = bt0 & 4095;
    int c0 = i2*2;
    float2 w0 = make_float2(w4[c0*4+0], w4[c0*4+4]);
    float2 w1 = make_float2(w4[c0*4+1], w4[c0*4+5]);
    float2 w2 = make_float2(w4[c0*4+2], w4[c0*4+6]);
    float2 w3 = make_float2(w4[c0*4+3], w4[c0*4+7]);
    float2 bb = make_float2(cb[c0], cb[c0+1]);
    const __half2* base = (const __half2*)(xp + ((size_t)(b << 12)) * (2*INNER)) + i2;
    __half2* out = (__half2*)(xc + ((size_t)bt0)*INNER) + i2;
    float2 z = make_float2(0.f, 0.f);
    float2 x0 = (t0-3 >= 0) ? __half22float2(base[(size_t)(t0-3)*512]) : z;
    float2 x1 = (t0-2 >= 0) ? __half22float2(base[(size_t)(t0-2)*512]) : z;
    float2 x2 = (t0-1 >= 0) ? __half22float2(base[(size_t)(t0-1)*512]) : z;
#pragma unroll
    for (int dt = 0; dt < CTT; dt++) {
        float2 x3 = __half22float2(base[(size_t)(t0+dt)*512]);
        float rx = w0.x*x0.x + w1.x*x1.x + w2.x*x2.x + w3.x*x3.x + bb.x;
        float ry = w0.y*x0.y + w1.y*x1.y + w2.y*x2.y + w3.y*x3.y + bb.y;
        out[(size_t)dt*256] = __floats2half2_rn(siluf(rx), siluf(ry));
        x0 = x1; x1 = x2; x2 = x3;
    }
}

// ---------------- chunked decaying scan: h = 0.95 h + 0.05 u (fp16 io, fp32 acc) ----------------
#define SCH 128
#define SWARM 256
__global__ void scan_kernel(const __half* __restrict__ u, __half* __restrict__ hs)
{
    int s = threadIdx.x;   // 64
    int b = blockIdx.y;
    int t0 = blockIdx.x * SCH;
    int tw = t0 - SWARM; if (tw < 0) tw = 0;
    const __half* ub = u  + ((size_t)b << 12)*Sdim + s;
    __half*       hb = hs + ((size_t)b << 12)*Sdim + s;
    float h = 0.f;
    for (int t = tw; t < t0; t++)
        h = 0.95f*h + 0.05f*__half2float(ub[(size_t)t*Sdim]);
#pragma unroll 4
    for (int t = t0; t < t0 + SCH; t++) {
        h = 0.95f*h + 0.05f*__half2float(ub[(size_t)t*Sdim]);
        hb[(size_t)t*Sdim] = __float2half(h);
    }
}

// ---------------- layernorm over H=256 (fp32 in place + fp16 shadow) ----------------
__global__ void ln_kernel(float* __restrict__ x, const float* __restrict__ g,
                          const float* __restrict__ b, __half* __restrict__ xh)
{
    int m = blockIdx.x;
    int h = threadIdx.x;   // 256
    float v = x[(size_t)m*Hdim + h];
    float s1 = v, s2 = v*v;
#pragma unroll
    for (int o = 16; o > 0; o >>= 1) {
        s1 += __shfl_xor_sync(0xffffffffu, s1, o);
        s2 += __shfl_xor_sync(0xffffffffu, s2, o);
    }
    __shared__ float r1[8], r2[8];
    int wid = h >> 5, lane = h & 31;
    if (lane == 0) { r1[wid] = s1; r2[wid] = s2; }
    __syncthreads();
    if (h == 0) {
        float a = 0.f, c = 0.f;
#pragma unroll
        for (int i = 0; i < 8; i++) { a += r1[i]; c += r2[i]; }
        r1[0] = a; r2[0] = c;
    }
    __syncthreads();
    float mean = r1[0] * (1.f/256.f);
    float var  = r2[0] * (1.f/256.f) - mean*mean;
    float r = (v - mean)*rsqrtf(var + 1e-5f)*g[h] + b[h];
    x[(size_t)m*Hdim + h] = r;
    xh[(size_t)m*Hdim + h] = __float2half(r);
}

// ---------------- layernorm over H=256 (fp16 in place) ----------------
__global__ void ln_h_kernel(__half* __restrict__ x, const float* __restrict__ g, const float* __restrict__ b)
{
    int m = blockIdx.x;
    int h = threadIdx.x;   // 256
    float v = __half2float(x[(size_t)m*Hdim + h]);
    float s1 = v, s2 = v*v;
#pragma unroll
    for (int o = 16; o > 0; o >>= 1) {
        s1 += __shfl_xor_sync(0xffffffffu, s1, o);
        s2 += __shfl_xor_sync(0xffffffffu, s2, o);
    }
    __shared__ float r1[8], r2[8];
    int wid = h >> 5, lane = h & 31;
    if (lane == 0) { r1[wid] = s1; r2[wid] = s2; }
    __syncthreads();
    if (h == 0) {
        float a = 0.f, c = 0.f;
#pragma unroll
        for (int i = 0; i < 8; i++) { a += r1[i]; c += r2[i]; }
        r1[0] = a; r2[0] = c;
    }
    __syncthreads();
    float mean = r1[0] * (1.f/256.f);
    float var  = r2[0] * (1.f/256.f) - mean*mean;
    x[(size_t)m*Hdim + h] = __float2half((v - mean)*rsqrtf(var + 1e-5f)*g[h] + b[h]);
}

// ---------------- pat_w repack to fp16: [i][o][c][k] -> [(i*3+k)][o][c] ----------------
__global__ void repack_patw(const float* __restrict__ pw, __half* __restrict__ out)
{
    int idx = blockIdx.x*256 + threadIdx.x;
    if (idx >= 4*64*256*3) return;
    int k = idx % 3;
    int c = (idx/3) % 256;
    int o = (idx/768) % 64;
    int i = idx / 49152;
    out[((size_t)(i*3 + k)*64 + o)*256 + c] = __float2half(pw[idx]);
}

// ================= fp16 MMA GEMM (ldmatrix fragments, reg-double-buffered staging) =================
// BM=128, BN=NT, BK=32, 256 threads / 8 warps. A, B fp16 in gmem.
// EPI 0: plain store          EPI 1: (acc + bias[n]*xc[m,n]) * silu(xg[m,n])
// EPI 2: acc + aux1f[m,n]     EPI 4: relu(acc + bias[n])
// EPI 5: acc + bias[n], scatter to [b][c][t][v]
// A2/ksplit: A source switches to A2 for k >= ksplit.
template<int NT, int EPI, bool OH>
__global__ __launch_bounds__(256) void gemm_h(
    const __half* __restrict__ A, int lda,
    const __half* __restrict__ A2, int lda2, int ksplit,
    const __half* __restrict__ Bmat, int ldb,
    void* __restrict__ Cv, int ldc, int K,
    const float* __restrict__ bias,
    const void* __restrict__ aux1v, int ld1,
    const void* __restrict__ aux2v, int ld2)
{
    constexpr int WRM = (NT == 128) ? 2 : 4;
    constexpr int WRN = 8 / WRM;
    constexpr int WM  = 128 / WRM;
    constexpr int WN  = NT / WRN;
    constexpr int MF  = WM / 16;
    constexpr int NF  = WN / 8;
    constexpr int AI  = 2;
    constexpr int BI  = (NT * 4) / 256;

    __shared__ __align__(16) uint32_t As[128][20];
    __shared__ __align__(16) uint32_t Bs[NT][20];

    const int bm = blockIdx.y * 128;
    const int bn = blockIdx.x * NT;
    const int tid = threadIdx.x;
    const int lane = tid & 31, wid = tid >> 5;
    const int gid = lane >> 2, tg = lane & 3;
    const int wm0 = (wid % WRM) * WM;
    const int wn0 = (wid / WRM) * WN;

    // ldmatrix per-lane address components
    const int grp = lane >> 3, lr8 = lane & 7;
    const uint32_t sAbase = smem_u32(&As[0][0]);
    const uint32_t sBbase = smem_u32(&Bs[0][0]);
    // A x4: mat0 m0-7/k0-7, mat1 m8-15/k0-7, mat2 m0-7/k8-15, mat3 m8-15/k8-15
    const uint32_t aAddr = sAbase + (((wm0 + (grp & 1)*8 + lr8) * 20) + (grp >> 1)*4) * 4;
    // B x4 (two n-strips): mat0 n0-7/k0-7, mat1 n0-7/k8-15, mat2 n8-15/k0-7, mat3 n8-15/k8-15
    const uint32_t bAddr = sBbase + (((wn0 + (grp >> 1)*8 + lr8) * 20) + (grp & 1)*4) * 4;

    uint4 rah[AI], rbh[BI];

    auto loadA = [&](int c) {
        int kk = c * 32;
        const __half* Asrc = A; int ldA = lda;
        if (kk >= ksplit) { Asrc = A2; kk -= ksplit; ldA = lda2; }
#pragma unroll
        for (int i = 0; i < AI; i++) {
            int idx = tid + 256*i;
            int row = idx >> 2, seg = idx & 3;
            rah[i] = *(const uint4*)(Asrc + (size_t)(bm + row)*ldA + kk + seg*8);
        }
    };
    auto loadB = [&](int c) {
        int kk = c * 32;
#pragma unroll
        for (int i = 0; i < BI; i++) {
            int idx = tid + 256*i;
            int row = idx >> 2, seg = idx & 3;
            rbh[i] = *(const uint4*)(Bmat + (size_t)(bn + row)*ldb + kk + seg*8);
        }
    };

    float acc[MF][NF][4] = {};

    loadA(0); loadB(0);
    const int NC = K / 32;
    for (int c = 0; c < NC; c++) {
        __syncthreads();
#pragma unroll
        for (int i = 0; i < AI; i++) {
            int idx = tid + 256*i;
            int row = idx >> 2, seg = idx & 3;
            *(uint4*)&As[row][seg*4] = rah[i];
        }
#pragma unroll
        for (int i = 0; i < BI; i++) {
            int idx = tid + 256*i;
            int row = idx >> 2, seg = idx & 3;
            *(uint4*)&Bs[row][seg*4] = rbh[i];
        }
        __syncthreads();
        if (c + 1 < NC) { loadA(c + 1); loadB(c + 1); }

#pragma unroll
        for (int s = 0; s < 2; s++) {
            const int kb = s * 8;
            uint32_t af[MF][4], bf[NF][2];
#pragma unroll
            for (int mf = 0; mf < MF; mf++)
                ldsm4(af[mf], aAddr + (mf*16*20 + kb)*4);
#pragma unroll
            for (int np = 0; np < NF/2; np++) {
                uint32_t r[4];
                ldsm4(r, bAddr + (np*16*20 + kb)*4);
                bf[2*np    ][0] = r[0]; bf[2*np    ][1] = r[1];
                bf[2*np + 1][0] = r[2]; bf[2*np + 1][1] = r[3];
            }
#pragma unroll
            for (int mf = 0; mf < MF; mf++)
#pragma unroll
                for (int nf = 0; nf < NF; nf++)
                    mma16(acc[mf][nf], af[mf], bf[nf]);
        }
    }

    // epilogue
    const __half* aux1h = (const __half*)aux1v;
    const __half* aux2h = (const __half*)aux2v;
    const float*  aux1f = (const float*)aux1v;
    float* Cf = (float*)Cv;
    __half* Ch = (__half*)Cv;
#pragma unroll
    for (int mf = 0; mf < MF; mf++) {
#pragma unroll
        for (int nf = 0; nf < NF; nf++) {
            int mbase = bm + wm0 + mf*16 + gid;
            int n = bn + wn0 + nf*8 + tg*2;
#pragma unroll
            for (int hh = 0; hh < 2; hh++) {
                int m = mbase + hh*8;
                float v0 = acc[mf][nf][hh*2 + 0];
                float v1 = acc[mf][nf][hh*2 + 1];
                if (EPI == 1) {
                    v0 = (v0 + bias[n  ]*__half2float(aux1h[(size_t)m*ld1 + n  ]))
                         * siluf(__half2float(aux2h[(size_t)m*ld2 + n  ]));
                    v1 = (v1 + bias[n+1]*__half2float(aux1h[(size_t)m*ld1 + n+1]))
                         * siluf(__half2float(aux2h[(size_t)m*ld2 + n+1]));
                } else if (EPI == 2) {
                    v0 += aux1f[(size_t)m*ld1 + n];
                    v1 += aux1f[(size_t)m*ld1 + n + 1];
                } else if (EPI == 4) {
                    v0 = fmaxf(v0 + bias[n    ], 0.f);
                    v1 = fmaxf(v1 + bias[n + 1], 0.f);
                } else if (EPI == 5) {
                    v0 += bias[n];
                    v1 += bias[n + 1];
                }
                if (EPI == 5) {
                    int b = m >> 12, t = m & 4095;
                    int cc = n >> 10, vv = n & 1023;
                    *(float2*)&Cf[(((size_t)(b*Cch + cc))*Tlen + t)*Vsz + vv] = make_float2(v0, v1);
                } else if (OH) {
                    *(float2*)&Cf[(size_t)m*ldc + n] = make_float2(v0, v1);
                } else {
                    *(__half2*)&Ch[(size_t)m*ldc + n] = __floats2half2_rn(v0, v1);
                }
            }
        }
    }
}

// ================= pattern convs: 4 dilations, 3 taps, ldmatrix fragments =================
// grid (4, M/128). A = emb_h fp16, B = patw fp16, C = pat fp16. 256 threads.
__global__ __launch_bounds__(256) void pat_h(
    const __half* __restrict__ A,
    const __half* __restrict__ Bw,
    const float* __restrict__ bias,
    __half* __restrict__ C)
{
    __shared__ __align__(16) uint32_t As[128][20];
    __shared__ __align__(16) uint32_t Bs[64][20];
    const int di = blockIdx.x;
    const int dlut[4] = {1, 3, 6, 12};
    const int d = dlut[di];
    const int bm = blockIdx.y * 128;
    const int tid = threadIdx.x;
    const int lane = tid & 31, wid = tid >> 5;
    const int gid = lane >> 2, tg = lane & 3;
    const int wm0 = (wid & 3) * 32;
    const int wn0 = (wid >> 2) * 32;

    const int grp = lane >> 3, lr8 = lane & 7;
    const uint32_t aAddr = smem_u32(&As[0][0]) + (((wm0 + (grp & 1)*8 + lr8) * 20) + (grp >> 1)*4) * 4;
    const uint32_t bAddr = smem_u32(&Bs[0][0]) + (((wn0 + (grp >> 1)*8 + lr8) * 20) + (grp & 1)*4) * 4;

    float acc[2][4][4] = {};

    for (int tap = 0; tap < 3; tap++) {
        const int shift = (tap - 1) * d;
        const __half* Bp = Bw + (size_t)(di*3 + tap)*64*256;
        for (int c = 0; c < 8; c++) {
            const int kk = c * 32;
            __syncthreads();
#pragma unroll
            for (int i = 0; i < 2; i++) {
                int idx = tid + 256*i;
                int row = idx >> 2, seg = idx & 3;
                int m = bm + row;
                int t = m & 4095, tt = t + shift;
                uint4 u = make_uint4(0u, 0u, 0u, 0u);
                if (tt >= 0 && tt < 4096)
                    u = *(const uint4*)(A + (size_t)((m & ~4095) + tt)*256 + kk + seg*8);
                *(uint4*)&As[row][seg*4] = u;
            }
            {
                int row = tid >> 2, seg = tid & 3;
                *(uint4*)&Bs[row][seg*4] = *(const uint4*)(Bp + (size_t)row*256 + kk + seg*8);
            }
            __syncthreads();

#pragma unroll
            for (int s = 0; s < 2; s++) {
                const int kb = s * 8;
                uint32_t af[2][4], bf[4][2];
#pragma unroll
                for (int mf = 0; mf < 2; mf++)
                    ldsm4(af[mf], aAddr + (mf*16*20 + kb)*4);
#pragma unroll
                for (int np = 0; np < 2; np++) {
                    uint32_t r[4];
                    ldsm4(r, bAddr + (np*16*20 + kb)*4);
                    bf[2*np    ][0] = r[0]; bf[2*np    ][1] = r[1];
                    bf[2*np + 1][0] = r[2]; bf[2*np + 1][1] = r[3];
                }
#pragma unroll
                for (int mf = 0; mf < 2; mf++)
#pragma unroll
                    for (int nf = 0; nf < 4; nf++)
                        mma16(acc[mf][nf], af[mf], bf[nf]);
            }
        }
    }

#pragma unroll
    for (int mf = 0; mf < 2; mf++) {
#pragma unroll
        for (int nf = 0; nf < 4; nf++) {
            int mbase = bm + wm0 + mf*16 + gid;
            int nl = wn0 + nf*8 + tg*2;
#pragma unroll
            for (int hh = 0; hh < 2; hh++) {
                int m = mbase + hh*8;
                __half2 hv = __floats2half2_rn(acc[mf][nf][hh*2+0] + bias[di*64 + nl],
                                               acc[mf][nf][hh*2+1] + bias[di*64 + nl + 1]);
                *(__half2*)&C[(size_t)m*256 + di*64 + nl] = hv;
            }
        }
    }
}

// ---------------- host launch ----------------
extern "C" void kernel_launch(void* const* d_in, const int* in_sizes, int n_in,
                              void* d_out, int out_size)
{
    const int*   tok     = (const int*)  d_in[0];
    const float* text    = (const float*)d_in[1];
    const float* tokemb  = (const float*)d_in[2];
    const float* posemb  = (const float*)d_in[3];
    const float* in_w    = (const float*)d_in[4];
    const float* conv_w  = (const float*)d_in[5];
    const float* conv_b  = (const float*)d_in[6];
    const float* Dw      = (const float*)d_in[7];
    const float* Bp_w    = (const float*)d_in[8];
    const float* Cp_w    = (const float*)d_in[9];
    const float* out_w   = (const float*)d_in[10];
    const float* ln_g    = (const float*)d_in[11];
    const float* ln_b    = (const float*)d_in[12];
    const float* pat_w   = (const float*)d_in[13];
    const float* pat_b   = (const float*)d_in[14];
    const float* fus_w   = (const float*)d_in[15];
    const float* fus_b   = (const float*)d_in[16];
    const float* fus_g   = (const float*)d_in[17];
    const float* fus_bb  = (const float*)d_in[18];
    const float* head_w  = (const float*)d_in[19];
    const float* head_b  = (const float*)d_in[20];
    const int*   pos_off = (const int*)  d_in[21];
    float* out = (float*)d_out;

    float *emb, *featA, *featB;
    __half *emb_h, *feat_h, *u, *hs, *xp, *xc, *z, *pat, *fused;
    __half *inw_h, *bpw_h, *cpw_h, *outw_h, *fusw_h, *headw_h, *patw_h;
    cudaGetSymbolAddress((void**)&emb,    g_emb);
    cudaGetSymbolAddress((void**)&featA,  g_featA);
    cudaGetSymbolAddress((void**)&featB,  g_featB);
    cudaGetSymbolAddress((void**)&emb_h,  g_emb_h);
    cudaGetSymbolAddress((void**)&feat_h, g_feat_h);
    cudaGetSymbolAddress((void**)&u,      g_u);
    cudaGetSymbolAddress((void**)&hs,     g_hs);
    cudaGetSymbolAddress((void**)&xp,     g_xp);
    cudaGetSymbolAddress((void**)&xc,     g_xc);
    cudaGetSymbolAddress((void**)&z,      g_z);
    cudaGetSymbolAddress((void**)&pat,    g_pat);
    cudaGetSymbolAddress((void**)&fused,  g_fused);
    cudaGetSymbolAddress((void**)&inw_h,  g_inw_h);
    cudaGetSymbolAddress((void**)&bpw_h,  g_bpw_h);
    cudaGetSymbolAddress((void**)&cpw_h,  g_cpw_h);
    cudaGetSymbolAddress((void**)&outw_h, g_outw_h);
    cudaGetSymbolAddress((void**)&fusw_h, g_fusw_h);
    cudaGetSymbolAddress((void**)&headw_h,g_headw_h);
    cudaGetSymbolAddress((void**)&patw_h, g_patw_h);

    const int M = Mrows;
    const int GY = M / 128;   // 128

    convert_all<<<(CTOT + 255)/256, 256>>>(in_w, inw_h, Bp_w, bpw_h, Cp_w, cpw_h,
                                           out_w, outw_h, fus_w, fusw_h, head_w, headw_h);
    repack_patw<<<(4*3*64*256 + 255)/256, 256>>>(pat_w, patw_h);
    embed_kernel<<<M, Hdim>>>(tok, text, tokemb, posemb, pos_off, emb, emb_h);

    float* cur = emb;
    __half* cur_h = emb_h;
    float* nxt = featA;
    for (int l = 0; l < Lnum; l++) {
        // xp = x @ in_w^T   (M x 1024, K=256), A fp16, C fp16 — NT=64 (occupancy experiment)
        gemm_h<64,0,false><<<dim3(1024/64, GY), 256>>>(
            cur_h, Hdim, cur_h, Hdim, 1<<30,
            inw_h + (size_t)l*2*INNER*Hdim, Hdim,
            xp, 2*INNER, Hdim, nullptr, nullptr, 0, nullptr, 0);
        // causal depthwise conv + silu (half2)
        conv_silu_kernel<<<M/CTT, 256>>>(xp, conv_w + (size_t)l*INNER*4, conv_b + l*INNER, xc);
        // u = xc @ Bp_w^T   (M x 64, K=512), C fp16
        gemm_h<64,0,false><<<dim3(1, GY), 256>>>(
            xc, INNER, xc, INNER, 1<<30,
            bpw_h + (size_t)l*Sdim*INNER, INNER,
            u, Sdim, INNER, nullptr, nullptr, 0, nullptr, 0);
        // parallel chunked scan (fp16 io, fp32 acc)
        scan_kernel<<<dim3(Tlen/SCH, Bsz), Sdim>>>(u, hs);
        // z = (hs @ Cp_w^T + D*xc) * silu(xg)   (M x 512, K=64), C fp16
        gemm_h<128,1,false><<<dim3(INNER/128, GY), 256>>>(
            hs, Sdim, hs, Sdim, 1<<30,
            cpw_h + (size_t)l*INNER*Sdim, Sdim,
            z, INNER, Sdim, Dw + l*INNER, xc, INNER, xp + INNER, 2*INNER);
        // nxt = z @ out_w^T + residual   (M x 256, K=512), C fp32
        gemm_h<128,2,true><<<dim3(Hdim/128, GY), 256>>>(
            z, INNER, z, INNER, 1<<30,
            outw_h + (size_t)l*Hdim*INNER, INNER,
            nxt, Hdim, INNER, nullptr, cur, Hdim, nullptr, 0);
        // LN in place + fp16 shadow for next layer's GEMM A
        ln_kernel<<<M, Hdim>>>(nxt, ln_g + l*Hdim, ln_b + l*Hdim, feat_h);
        cur = nxt;
        cur_h = feat_h;
        nxt = (l == 0) ? featB : featA;
    }
    // cur_h == final feat (fp16)

    // pattern convs: one launch, 4 dilation groups x 3 taps accumulated in-kernel
    pat_h<<<dim3(4, GY), 256>>>(emb_h, patw_h, pat_b, pat);

    // fused = relu(concat(feat,pat) @ fus_w^T + fus_b) — single K=512 GEMM,
    // A (feat_h) switches to A2 (pat) at k=256; then fp16 LN
    gemm_h<128,4,false><<<dim3(Hdim/128, GY), 256>>>(
        cur_h, Hdim, pat, Hdim, Hdim,
        fusw_h, 2*Hdim,
        fused, Hdim, 2*Hdim, fus_b, nullptr, 0, nullptr, 0);
    ln_h_kernel<<<M, Hdim>>>(fused, fus_g, fus_bb);

    // logits = fused @ head_w^T + head_b, scattered to [b][c][t][v]
    gemm_h<128,5,false><<<dim3((Cch*Vsz)/128, GY), 256>>>(
        fused, Hdim, fused, Hdim, 1<<30,
        headw_h, Hdim,
        out, 0, Hdim, head_b, nullptr, 0, nullptr, 0);
}

// round 14
// speedup vs baseline: 1.0980x; 1.0980x over previous
#include <cuda_runtime.h>
#include <cuda_fp16.h>
#include <cuda_bf16.h>
#include <cstdint>

#define Bsz 4
#define Cch 4
#define Tlen 4096
#define Hdim 256
#define INNER 512
#define Sdim 64
#define Lnum 3
#define Vsz 1024
#define Mrows (Bsz*Tlen)   // 16384

// ---------------- scratch (allocation-free rule: __device__ globals) ----------------
__device__ float  g_emb  [Bsz*Tlen*Hdim];     // fp32 residual chain
__device__ float  g_featA[Bsz*Tlen*Hdim];
__device__ float  g_featB[Bsz*Tlen*Hdim];
__device__ __half g_emb_h [Bsz*Tlen*Hdim];    // fp16 GEMM-A shadows
__device__ __half g_feat_h[Bsz*Tlen*Hdim];
__device__ __half g_u    [Bsz*Tlen*Sdim];
__device__ __half g_hs   [Bsz*Tlen*Sdim];
__device__ __half g_xp   [Bsz*Tlen*2*INNER];
__device__ __half g_xc   [Bsz*Tlen*INNER];
__device__ __half g_z    [Bsz*Tlen*INNER];
__device__ __half g_pat  [Bsz*Tlen*Hdim];
__device__ __half g_fused[Bsz*Tlen*Hdim];
// fp16 weight copies
__device__ __half g_inw_h [Lnum*2*INNER*Hdim];
__device__ __half g_bpw_h [Lnum*Sdim*INNER];
__device__ __half g_cpw_h [Lnum*INNER*Sdim];
__device__ __half g_outw_h[Lnum*Hdim*INNER];
__device__ __half g_fusw_h[Hdim*2*Hdim];
__device__ __half g_headw_h[Cch*Vsz*Hdim];
__device__ __half g_patw_h[4*3*64*Hdim];

__device__ __forceinline__ float siluf(float x) {
    return x * (1.0f / (1.0f + __expf(-x)));
}

__device__ __forceinline__ uint32_t smem_u32(const void* p) {
    uint32_t a;
    asm("{ .reg .u64 t; cvta.to.shared.u64 t, %1; cvt.u32.u64 %0, t; }" : "=r"(a) : "l"(p));
    return a;
}

__device__ __forceinline__ void mma16(float c[4], const uint32_t a[4], const uint32_t b[2]) {
    asm volatile(
        "mma.sync.aligned.m16n8k16.row.col.f32.f16.f16.f32 "
        "{%0,%1,%2,%3},{%4,%5,%6,%7},{%8,%9},{%0,%1,%2,%3};\n"
        : "+f"(c[0]), "+f"(c[1]), "+f"(c[2]), "+f"(c[3])
        : "r"(a[0]), "r"(a[1]), "r"(a[2]), "r"(a[3]), "r"(b[0]), "r"(b[1]));
}

__device__ __forceinline__ void ldsm4(uint32_t r[4], uint32_t addr) {
    asm volatile("ldmatrix.sync.aligned.m8n8.x4.shared.b16 {%0,%1,%2,%3}, [%4];"
        : "=r"(r[0]), "=r"(r[1]), "=r"(r[2]), "=r"(r[3]) : "r"(addr));
}

__device__ __forceinline__ uint32_t packh(float x, float y) {
    __half2 h = __floats2half2_rn(x, y);
    return *(uint32_t*)&h;
}

// ---------------- all weight conversions + pat_w repack in one launch ----------------
#define CS0 (Lnum*2*INNER*Hdim)          // 786432
#define CS1 (Lnum*Sdim*INNER)            // 98304
#define CS2 (Lnum*INNER*Sdim)            // 98304
#define CS3 (Lnum*Hdim*INNER)            // 393216
#define CS4 (Hdim*2*Hdim)                // 131072
#define CS5 (Cch*Vsz*Hdim)               // 1048576
#define CS6 (4*3*64*Hdim)                // 196608 (pat_w repack)
#define CTOT (CS0+CS1+CS2+CS3+CS4+CS5+CS6)
__global__ void convert_all(const float* __restrict__ w0, __half* __restrict__ o0,
                            const float* __restrict__ w1, __half* __restrict__ o1,
                            const float* __restrict__ w2, __half* __restrict__ o2,
                            const float* __restrict__ w3, __half* __restrict__ o3,
                            const float* __restrict__ w4, __half* __restrict__ o4,
                            const float* __restrict__ w5, __half* __restrict__ o5,
                            const float* __restrict__ pw, __half* __restrict__ o6)
{
    int idx = blockIdx.x*256 + threadIdx.x;
    if (idx >= CTOT) return;
    if (idx < CS0) { o0[idx] = __float2half(w0[idx]); return; }
    idx -= CS0;
    if (idx < CS1) { o1[idx] = __float2half(w1[idx]); return; }
    idx -= CS1;
    if (idx < CS2) { o2[idx] = __float2half(w2[idx]); return; }
    idx -= CS2;
    if (idx < CS3) { o3[idx] = __float2half(w3[idx]); return; }
    idx -= CS3;
    if (idx < CS4) { o4[idx] = __float2half(w4[idx]); return; }
    idx -= CS4;
    if (idx < CS5) { o5[idx] = __float2half(w5[idx]); return; }
    idx -= CS5;
    {
        int k = idx % 3;
        int c = (idx/3) % 256;
        int o = (idx/768) % 64;
        int i = idx / 49152;
        o6[((size_t)(i*3 + k)*64 + o)*256 + c] = __float2half(pw[idx]);
    }
}

// ---------------- embedding: warp-per-row (8 rows/block), float4 ----------------
__global__ __launch_bounds__(256) void embed_kernel(
    const int* __restrict__ tok, const float* __restrict__ text,
    const float* __restrict__ tok_emb, const float* __restrict__ pos_emb,
    const int* __restrict__ pos_off, float* __restrict__ out,
    __half* __restrict__ outh)
{
    int w = threadIdx.x >> 5, lane = threadIdx.x & 31;
    int bt = blockIdx.x*8 + w;
    int b = bt >> 12, t = bt & 4095;
    int off = pos_off[0];
    int h0 = lane*8;
    float4 a0 = make_float4(0.f,0.f,0.f,0.f), a1 = a0;
#pragma unroll
    for (int c = 0; c < Cch; c++) {
        int v = tok[(b*Cch + c)*Tlen + t];
        const float4* e = (const float4*)(tok_emb + ((size_t)(c*Vsz + v))*Hdim + h0);
        float4 e0 = e[0], e1 = e[1];
        a0.x += e0.x; a0.y += e0.y; a0.z += e0.z; a0.w += e0.w;
        a1.x += e1.x; a1.y += e1.y; a1.z += e1.z; a1.w += e1.w;
    }
    const float4* p = (const float4*)(pos_emb + (size_t)(off + t)*Hdim + h0);
    const float4* x = (const float4*)(text + b*Hdim + h0);
    float4 p0 = p[0], p1 = p[1], x0 = x[0], x1 = x[1];
    float4 r0 = make_float4(0.25f*a0.x + p0.x + x0.x, 0.25f*a0.y + p0.y + x0.y,
                            0.25f*a0.z + p0.z + x0.z, 0.25f*a0.w + p0.w + x0.w);
    float4 r1 = make_float4(0.25f*a1.x + p1.x + x1.x, 0.25f*a1.y + p1.y + x1.y,
                            0.25f*a1.z + p1.z + x1.z, 0.25f*a1.w + p1.w + x1.w);
    ((float4*)(out + (size_t)bt*Hdim + h0))[0] = r0;
    ((float4*)(out + (size_t)bt*Hdim + h0))[1] = r1;
    uint4 u;
    u.x = packh(r0.x, r0.y); u.y = packh(r0.z, r0.w);
    u.z = packh(r1.x, r1.y); u.w = packh(r1.z, r1.w);
    *(uint4*)(outh + (size_t)bt*Hdim + h0) = u;
}

// ---------------- causal depthwise conv (k=4) + bias + silu, half2 x 2 channels ----------------
#define CTT 16
__global__ void conv_silu_kernel(const __half* __restrict__ xp, const float* __restrict__ w4,
                                 const float* __restrict__ cb, __half* __restrict__ xc)
{
    int i2 = threadIdx.x;          // 0..255 -> channels 2*i2, 2*i2+1
    int bt0 = blockIdx.x * CTT;
    int b = bt0 >> 12;
    int t0 = bt0 & 4095;
    int c0 = i2*2;
    float2 w0 = make_float2(w4[c0*4+0], w4[c0*4+4]);
    float2 w1 = make_float2(w4[c0*4+1], w4[c0*4+5]);
    float2 w2 = make_float2(w4[c0*4+2], w4[c0*4+6]);
    float2 w3 = make_float2(w4[c0*4+3], w4[c0*4+7]);
    float2 bb = make_float2(cb[c0], cb[c0+1]);
    const __half2* base = (const __half2*)(xp + ((size_t)(b << 12)) * (2*INNER)) + i2;
    __half2* out = (__half2*)(xc + ((size_t)bt0)*INNER) + i2;
    float2 z = make_float2(0.f, 0.f);
    float2 x0 = (t0-3 >= 0) ? __half22float2(base[(size_t)(t0-3)*512]) : z;
    float2 x1 = (t0-2 >= 0) ? __half22float2(base[(size_t)(t0-2)*512]) : z;
    float2 x2 = (t0-1 >= 0) ? __half22float2(base[(size_t)(t0-1)*512]) : z;
#pragma unroll
    for (int dt = 0; dt < CTT; dt++) {
        float2 x3 = __half22float2(base[(size_t)(t0+dt)*512]);
        float rx = w0.x*x0.x + w1.x*x1.x + w2.x*x2.x + w3.x*x3.x + bb.x;
        float ry = w0.y*x0.y + w1.y*x1.y + w2.y*x2.y + w3.y*x3.y + bb.y;
        out[(size_t)dt*256] = __floats2half2_rn(siluf(rx), siluf(ry));
        x0 = x1; x1 = x2; x2 = x3;
    }
}

// ---------------- chunked decaying scan: h = 0.95 h + 0.05 u (fp16 io, fp32 acc) ----------------
#define SCH 128
#define SWARM 256
__global__ void scan_kernel(const __half* __restrict__ u, __half* __restrict__ hs)
{
    int s = threadIdx.x;   // 64
    int b = blockIdx.y;
    int t0 = blockIdx.x * SCH;
    int tw = t0 - SWARM; if (tw < 0) tw = 0;
    const __half* ub = u  + ((size_t)b << 12)*Sdim + s;
    __half*       hb = hs + ((size_t)b << 12)*Sdim + s;
    float h = 0.f;
    for (int t = tw; t < t0; t++)
        h = 0.95f*h + 0.05f*__half2float(ub[(size_t)t*Sdim]);
#pragma unroll 4
    for (int t = t0; t < t0 + SCH; t++) {
        h = 0.95f*h + 0.05f*__half2float(ub[(size_t)t*Sdim]);
        hb[(size_t)t*Sdim] = __float2half(h);
    }
}

// ---------------- layernorm: warp-per-row (8 rows/block), fp32 + fp16 shadow ----------------
__global__ __launch_bounds__(256) void ln_kernel(
    float* __restrict__ x, const float* __restrict__ g,
    const float* __restrict__ b, __half* __restrict__ xh)
{
    int w = threadIdx.x >> 5, lane = threadIdx.x & 31;
    int m = blockIdx.x*8 + w;
    int h0 = lane*8;
    float4* row = (float4*)(x + (size_t)m*Hdim + h0);
    float4 v0 = row[0], v1 = row[1];
    float s1 = v0.x+v0.y+v0.z+v0.w + v1.x+v1.y+v1.z+v1.w;
    float s2 = v0.x*v0.x+v0.y*v0.y+v0.z*v0.z+v0.w*v0.w
             + v1.x*v1.x+v1.y*v1.y+v1.z*v1.z+v1.w*v1.w;
#pragma unroll
    for (int o = 16; o > 0; o >>= 1) {
        s1 += __shfl_xor_sync(0xffffffffu, s1, o);
        s2 += __shfl_xor_sync(0xffffffffu, s2, o);
    }
    float mean = s1 * (1.f/256.f);
    float var  = s2 * (1.f/256.f) - mean*mean;
    float rs   = rsqrtf(var + 1e-5f);
    float4 g0 = ((const float4*)(g + h0))[0], g1 = ((const float4*)(g + h0))[1];
    float4 b0 = ((const float4*)(b + h0))[0], b1 = ((const float4*)(b + h0))[1];
    float4 r0 = make_float4((v0.x-mean)*rs*g0.x + b0.x, (v0.y-mean)*rs*g0.y + b0.y,
                            (v0.z-mean)*rs*g0.z + b0.z, (v0.w-mean)*rs*g0.w + b0.w);
    float4 r1 = make_float4((v1.x-mean)*rs*g1.x + b1.x, (v1.y-mean)*rs*g1.y + b1.y,
                            (v1.z-mean)*rs*g1.z + b1.z, (v1.w-mean)*rs*g1.w + b1.w);
    row[0] = r0; row[1] = r1;
    uint4 u;
    u.x = packh(r0.x, r0.y); u.y = packh(r0.z, r0.w);
    u.z = packh(r1.x, r1.y); u.w = packh(r1.z, r1.w);
    *(uint4*)(xh + (size_t)m*Hdim + h0) = u;
}

// ---------------- layernorm: warp-per-row, fp16 in place (fully static indexing) ----------------
__global__ __launch_bounds__(256) void ln_h_kernel(
    __half* __restrict__ x, const float* __restrict__ g, const float* __restrict__ b)
{
    int w = threadIdx.x >> 5, lane = threadIdx.x & 31;
    int m = blockIdx.x*8 + w;
    int h0 = lane*8;
    uint4 raw = *(uint4*)(x + (size_t)m*Hdim + h0);
    float2 f0 = __half22float2(*(__half2*)&raw.x);
    float2 f1 = __half22float2(*(__half2*)&raw.y);
    float2 f2 = __half22float2(*(__half2*)&raw.z);
    float2 f3 = __half22float2(*(__half2*)&raw.w);
    float s1 = f0.x+f0.y + f1.x+f1.y + f2.x+f2.y + f3.x+f3.y;
    float s2 = f0.x*f0.x+f0.y*f0.y + f1.x*f1.x+f1.y*f1.y
             + f2.x*f2.x+f2.y*f2.y + f3.x*f3.x+f3.y*f3.y;
#pragma unroll
    for (int o = 16; o > 0; o >>= 1) {
        s1 += __shfl_xor_sync(0xffffffffu, s1, o);
        s2 += __shfl_xor_sync(0xffffffffu, s2, o);
    }
    float mean = s1 * (1.f/256.f);
    float var  = s2 * (1.f/256.f) - mean*mean;
    float rs   = rsqrtf(var + 1e-5f);
    float4 g0 = ((const float4*)(g + h0))[0], g1 = ((const float4*)(g + h0))[1];
    float4 b0 = ((const float4*)(b + h0))[0], b1 = ((const float4*)(b + h0))[1];
    float n0 = (f0.x-mean)*rs*g0.x + b0.x;
    float n1 = (f0.y-mean)*rs*g0.y + b0.y;
    float n2 = (f1.x-mean)*rs*g0.z + b0.z;
    float n3 = (f1.y-mean)*rs*g0.w + b0.w;
    float n4 = (f2.x-mean)*rs*g1.x + b1.x;
    float n5 = (f2.y-mean)*rs*g1.y + b1.y;
    float n6 = (f3.x-mean)*rs*g1.z + b1.z;
    float n7 = (f3.y-mean)*rs*g1.w + b1.w;
    uint4 u;
    u.x = packh(n0, n1); u.y = packh(n2, n3);
    u.z = packh(n4, n5); u.w = packh(n6, n7);
    *(uint4*)(x + (size_t)m*Hdim + h0) = u;
}

// ================= fp16 MMA GEMM (R8 champion: ldmatrix, single buffer, 256 thr) =================
// BM=128, BN=NT, BK=32, 256 threads / 8 warps.
// NT=128: warps 2m x 4n (64x32 warp tiles). NT=64: warps 4m x 2n (32x32).
// EPI 0: plain store          EPI 1: (acc + bias[n]*xc[m,n]) * silu(xg[m,n])
// EPI 2: acc + aux1f[m,n]     EPI 4: relu(acc + bias[n])
// EPI 5: acc + bias[n], scatter to [b][c][t][v]
// A2/ksplit: A source switches to A2 for k >= ksplit.
template<int NT, int EPI, bool OH>
__global__ __launch_bounds__(256) void gemm_h(
    const __half* __restrict__ A, int lda,
    const __half* __restrict__ A2, int lda2, int ksplit,
    const __half* __restrict__ Bmat, int ldb,
    void* __restrict__ Cv, int ldc, int K,
    const float* __restrict__ bias,
    const void* __restrict__ aux1v, int ld1,
    const void* __restrict__ aux2v, int ld2)
{
    constexpr int WRM = (NT == 128) ? 2 : 4;
    constexpr int WRN = 8 / WRM;
    constexpr int WM  = 128 / WRM;
    constexpr int WN  = NT / WRN;
    constexpr int MF  = WM / 16;
    constexpr int NF  = WN / 8;
    constexpr int AI  = 2;
    constexpr int BI  = (NT * 4) / 256;

    __shared__ __align__(16) uint32_t As[128][20];
    __shared__ __align__(16) uint32_t Bs[NT][20];

    const int bm = blockIdx.y * 128;
    const int bn = blockIdx.x * NT;
    const int tid = threadIdx.x;
    const int lane = tid & 31, wid = tid >> 5;
    const int gid = lane >> 2, tg = lane & 3;
    const int wm0 = (wid % WRM) * WM;
    const int wn0 = (wid / WRM) * WN;

    const int grp = lane >> 3, lr8 = lane & 7;
    const uint32_t sAbase = smem_u32(&As[0][0]);
    const uint32_t sBbase = smem_u32(&Bs[0][0]);
    const uint32_t aAddr = sAbase + (((wm0 + (grp & 1)*8 + lr8) * 20) + (grp >> 1)*4) * 4;
    const uint32_t bAddr = sBbase + (((wn0 + (grp >> 1)*8 + lr8) * 20) + (grp & 1)*4) * 4;

    uint4 rah[AI], rbh[BI];

    auto loadA = [&](int c) {
        int kk = c * 32;
        const __half* Asrc = A; int ldA = lda;
        if (kk >= ksplit) { Asrc = A2; kk -= ksplit; ldA = lda2; }
#pragma unroll
        for (int i = 0; i < AI; i++) {
            int idx = tid + 256*i;
            int row = idx >> 2, seg = idx & 3;
            rah[i] = *(const uint4*)(Asrc + (size_t)(bm + row)*ldA + kk + seg*8);
        }
    };
    auto loadB = [&](int c) {
        int kk = c * 32;
#pragma unroll
        for (int i = 0; i < BI; i++) {
            int idx = tid + 256*i;
            int row = idx >> 2, seg = idx & 3;
            rbh[i] = *(const uint4*)(Bmat + (size_t)(bn + row)*ldb + kk + seg*8);
        }
    };

    float acc[MF][NF][4] = {};

    loadA(0); loadB(0);
    const int NC = K / 32;
    for (int c = 0; c < NC; c++) {
        __syncthreads();
#pragma unroll
        for (int i = 0; i < AI; i++) {
            int idx = tid + 256*i;
            int row = idx >> 2, seg = idx & 3;
            *(uint4*)&As[row][seg*4] = rah[i];
        }
#pragma unroll
        for (int i = 0; i < BI; i++) {
            int idx = tid + 256*i;
            int row = idx >> 2, seg = idx & 3;
            *(uint4*)&Bs[row][seg*4] = rbh[i];
        }
        __syncthreads();
        if (c + 1 < NC) { loadA(c + 1); loadB(c + 1); }

#pragma unroll
        for (int s = 0; s < 2; s++) {
            const int kb = s * 8;
            uint32_t af[MF][4], bf[NF][2];
#pragma unroll
            for (int mf = 0; mf < MF; mf++)
                ldsm4(af[mf], aAddr + (mf*16*20 + kb)*4);
#pragma unroll
            for (int np = 0; np < NF/2; np++) {
                uint32_t r[4];
                ldsm4(r, bAddr + (np*16*20 + kb)*4);
                bf[2*np    ][0] = r[0]; bf[2*np    ][1] = r[1];
                bf[2*np + 1][0] = r[2]; bf[2*np + 1][1] = r[3];
            }
#pragma unroll
            for (int mf = 0; mf < MF; mf++)
#pragma unroll
                for (int nf = 0; nf < NF; nf++)
                    mma16(acc[mf][nf], af[mf], bf[nf]);
        }
    }

    // epilogue
    const __half* aux1h = (const __half*)aux1v;
    const __half* aux2h = (const __half*)aux2v;
    const float*  aux1f = (const float*)aux1v;
    float* Cf = (float*)Cv;
    __half* Ch = (__half*)Cv;
#pragma unroll
    for (int mf = 0; mf < MF; mf++) {
#pragma unroll
        for (int nf = 0; nf < NF; nf++) {
            int mbase = bm + wm0 + mf*16 + gid;
            int n = bn + wn0 + nf*8 + tg*2;
#pragma unroll
            for (int hh = 0; hh < 2; hh++) {
                int m = mbase + hh*8;
                float v0 = acc[mf][nf][hh*2 + 0];
                float v1 = acc[mf][nf][hh*2 + 1];
                if (EPI == 1) {
                    v0 = (v0 + bias[n  ]*__half2float(aux1h[(size_t)m*ld1 + n  ]))
                         * siluf(__half2float(aux2h[(size_t)m*ld2 + n  ]));
                    v1 = (v1 + bias[n+1]*__half2float(aux1h[(size_t)m*ld1 + n+1]))
                         * siluf(__half2float(aux2h[(size_t)m*ld2 + n+1]));
                } else if (EPI == 2) {
                    v0 += aux1f[(size_t)m*ld1 + n];
                    v1 += aux1f[(size_t)m*ld1 + n + 1];
                } else if (EPI == 4) {
                    v0 = fmaxf(v0 + bias[n    ], 0.f);
                    v1 = fmaxf(v1 + bias[n + 1], 0.f);
                } else if (EPI == 5) {
                    v0 += bias[n];
                    v1 += bias[n + 1];
                }
                if (EPI == 5) {
                    int b = m >> 12, t = m & 4095;
                    int cc = n >> 10, vv = n & 1023;
                    *(float2*)&Cf[(((size_t)(b*Cch + cc))*Tlen + t)*Vsz + vv] = make_float2(v0, v1);
                } else if (OH) {
                    *(float2*)&Cf[(size_t)m*ldc + n] = make_float2(v0, v1);
                } else {
                    *(__half2*)&Ch[(size_t)m*ldc + n] = __floats2half2_rn(v0, v1);
                }
            }
        }
    }
}

// ================= pattern convs: 4 dilations, 3 taps, ldmatrix fragments (R8-proven) =================
__global__ __launch_bounds__(256) void pat_h(
    const __half* __restrict__ A,
    const __half* __restrict__ Bw,
    const float* __restrict__ bias,
    __half* __restrict__ C)
{
    __shared__ __align__(16) uint32_t As[128][20];
    __shared__ __align__(16) uint32_t Bs[64][20];
    const int di = blockIdx.x;
    const int dlut[4] = {1, 3, 6, 12};
    const int d = dlut[di];
    const int bm = blockIdx.y * 128;
    const int tid = threadIdx.x;
    const int lane = tid & 31, wid = tid >> 5;
    const int gid = lane >> 2, tg = lane & 3;
    const int wm0 = (wid & 3) * 32;
    const int wn0 = (wid >> 2) * 32;

    const int grp = lane >> 3, lr8 = lane & 7;
    const uint32_t aAddr = smem_u32(&As[0][0]) + (((wm0 + (grp & 1)*8 + lr8) * 20) + (grp >> 1)*4) * 4;
    const uint32_t bAddr = smem_u32(&Bs[0][0]) + (((wn0 + (grp >> 1)*8 + lr8) * 20) + (grp & 1)*4) * 4;

    float acc[2][4][4] = {};

    for (int tap = 0; tap < 3; tap++) {
        const int shift = (tap - 1) * d;
        const __half* Bp = Bw + (size_t)(di*3 + tap)*64*256;
        for (int c = 0; c < 8; c++) {
            const int kk = c * 32;
            __syncthreads();
#pragma unroll
            for (int i = 0; i < 2; i++) {
                int idx = tid + 256*i;
                int row = idx >> 2, seg = idx & 3;
                int m = bm + row;
                int t = m & 4095, tt = t + shift;
                uint4 u = make_uint4(0u, 0u, 0u, 0u);
                if (tt >= 0 && tt < 4096)
                    u = *(const uint4*)(A + (size_t)((m & ~4095) + tt)*256 + kk + seg*8);
                *(uint4*)&As[row][seg*4] = u;
            }
            {
                int row = tid >> 2, seg = tid & 3;
                *(uint4*)&Bs[row][seg*4] = *(const uint4*)(Bp + (size_t)row*256 + kk + seg*8);
            }
            __syncthreads();

#pragma unroll
            for (int s = 0; s < 2; s++) {
                const int kb = s * 8;
                uint32_t af[2][4], bf[4][2];
#pragma unroll
                for (int mf = 0; mf < 2; mf++)
                    ldsm4(af[mf], aAddr + (mf*16*20 + kb)*4);
#pragma unroll
                for (int np = 0; np < 2; np++) {
                    uint32_t r[4];
                    ldsm4(r, bAddr + (np*16*20 + kb)*4);
                    bf[2*np    ][0] = r[0]; bf[2*np    ][1] = r[1];
                    bf[2*np + 1][0] = r[2]; bf[2*np + 1][1] = r[3];
                }
#pragma unroll
                for (int mf = 0; mf < 2; mf++)
#pragma unroll
                    for (int nf = 0; nf < 4; nf++)
                        mma16(acc[mf][nf], af[mf], bf[nf]);
            }
        }
    }

#pragma unroll
    for (int mf = 0; mf < 2; mf++) {
#pragma unroll
        for (int nf = 0; nf < 4; nf++) {
            int mbase = bm + wm0 + mf*16 + gid;
            int nl = wn0 + nf*8 + tg*2;
#pragma unroll
            for (int hh = 0; hh < 2; hh++) {
                int m = mbase + hh*8;
                __half2 hv = __floats2half2_rn(acc[mf][nf][hh*2+0] + bias[di*64 + nl],
                                               acc[mf][nf][hh*2+1] + bias[di*64 + nl + 1]);
                *(__half2*)&C[(size_t)m*256 + di*64 + nl] = hv;
            }
        }
    }
}

// ---------------- host launch ----------------
extern "C" void kernel_launch(void* const* d_in, const int* in_sizes, int n_in,
                              void* d_out, int out_size)
{
    const int*   tok     = (const int*)  d_in[0];
    const float* text    = (const float*)d_in[1];
    const float* tokemb  = (const float*)d_in[2];
    const float* posemb  = (const float*)d_in[3];
    const float* in_w    = (const float*)d_in[4];
    const float* conv_w  = (const float*)d_in[5];
    const float* conv_b  = (const float*)d_in[6];
    const float* Dw      = (const float*)d_in[7];
    const float* Bp_w    = (const float*)d_in[8];
    const float* Cp_w    = (const float*)d_in[9];
    const float* out_w   = (const float*)d_in[10];
    const float* ln_g    = (const float*)d_in[11];
    const float* ln_b    = (const float*)d_in[12];
    const float* pat_w   = (const float*)d_in[13];
    const float* pat_b   = (const float*)d_in[14];
    const float* fus_w   = (const float*)d_in[15];
    const float* fus_b   = (const float*)d_in[16];
    const float* fus_g   = (const float*)d_in[17];
    const float* fus_bb  = (const float*)d_in[18];
    const float* head_w  = (const float*)d_in[19];
    const float* head_b  = (const float*)d_in[20];
    const int*   pos_off = (const int*)  d_in[21];
    float* out = (float*)d_out;

    float *emb, *featA, *featB;
    __half *emb_h, *feat_h, *u, *hs, *xp, *xc, *z, *pat, *fused;
    __half *inw_h, *bpw_h, *cpw_h, *outw_h, *fusw_h, *headw_h, *patw_h;
    cudaGetSymbolAddress((void**)&emb,    g_emb);
    cudaGetSymbolAddress((void**)&featA,  g_featA);
    cudaGetSymbolAddress((void**)&featB,  g_featB);
    cudaGetSymbolAddress((void**)&emb_h,  g_emb_h);
    cudaGetSymbolAddress((void**)&feat_h, g_feat_h);
    cudaGetSymbolAddress((void**)&u,      g_u);
    cudaGetSymbolAddress((void**)&hs,     g_hs);
    cudaGetSymbolAddress((void**)&xp,     g_xp);
    cudaGetSymbolAddress((void**)&xc,     g_xc);
    cudaGetSymbolAddress((void**)&z,      g_z);
    cudaGetSymbolAddress((void**)&pat,    g_pat);
    cudaGetSymbolAddress((void**)&fused,  g_fused);
    cudaGetSymbolAddress((void**)&inw_h,  g_inw_h);
    cudaGetSymbolAddress((void**)&bpw_h,  g_bpw_h);
    cudaGetSymbolAddress((void**)&cpw_h,  g_cpw_h);
    cudaGetSymbolAddress((void**)&outw_h, g_outw_h);
    cudaGetSymbolAddress((void**)&fusw_h, g_fusw_h);
    cudaGetSymbolAddress((void**)&headw_h,g_headw_h);
    cudaGetSymbolAddress((void**)&patw_h, g_patw_h);

    const int M = Mrows;
    const int GY = M / 128;   // 128

    convert_all<<<(CTOT + 255)/256, 256>>>(in_w, inw_h, Bp_w, bpw_h, Cp_w, cpw_h,
                                           out_w, outw_h, fus_w, fusw_h, head_w, headw_h,
                                           pat_w, patw_h);
    embed_kernel<<<M/8, 256>>>(tok, text, tokemb, posemb, pos_off, emb, emb_h);

    float* cur = emb;
    __half* cur_h = emb_h;
    float* nxt = featA;
    for (int l = 0; l < Lnum; l++) {
        // xp = x @ in_w^T   (M x 1024, K=256), A fp16, C fp16
        gemm_h<128,0,false><<<dim3(1024/128, GY), 256>>>(
            cur_h, Hdim, cur_h, Hdim, 1<<30,
            inw_h + (size_t)l*2*INNER*Hdim, Hdim,
            xp, 2*INNER, Hdim, nullptr, nullptr, 0, nullptr, 0);
        // causal depthwise conv + silu (half2)
        conv_silu_kernel<<<M/CTT, 256>>>(xp, conv_w + (size_t)l*INNER*4, conv_b + l*INNER, xc);
        // u = xc @ Bp_w^T   (M x 64, K=512), C fp16
        gemm_h<64,0,false><<<dim3(1, GY), 256>>>(
            xc, INNER, xc, INNER, 1<<30,
            bpw_h + (size_t)l*Sdim*INNER, INNER,
            u, Sdim, INNER, nullptr, nullptr, 0, nullptr, 0);
        // parallel chunked scan (fp16 io, fp32 acc)
        scan_kernel<<<dim3(Tlen/SCH, Bsz), Sdim>>>(u, hs);
        // z = (hs @ Cp_w^T + D*xc) * silu(xg)   (M x 512, K=64), C fp16
        gemm_h<128,1,false><<<dim3(INNER/128, GY), 256>>>(
            hs, Sdim, hs, Sdim, 1<<30,
            cpw_h + (size_t)l*INNER*Sdim, Sdim,
            z, INNER, Sdim, Dw + l*INNER, xc, INNER, xp + INNER, 2*INNER);
        // nxt = z @ out_w^T + residual   (M x 256, K=512), C fp32
        gemm_h<128,2,true><<<dim3(Hdim/128, GY), 256>>>(
            z, INNER, z, INNER, 1<<30,
            outw_h + (size_t)l*Hdim*INNER, INNER,
            nxt, Hdim, INNER, nullptr, cur, Hdim, nullptr, 0);
        // LN in place + fp16 shadow for next layer's GEMM A (warp-per-row)
        ln_kernel<<<M/8, 256>>>(nxt, ln_g + l*Hdim, ln_b + l*Hdim, feat_h);
        cur = nxt;
        cur_h = feat_h;
        nxt = (l == 0) ? featB : featA;
    }
    // cur_h == final feat (fp16)

    // pattern convs: one launch, 4 dilation groups x 3 taps accumulated in-kernel
    pat_h<<<dim3(4, GY), 256>>>(emb_h, patw_h, pat_b, pat);

    // fused = relu(concat(feat,pat) @ fus_w^T + fus_b) — single K=512 GEMM,
    // A (feat_h) switches to A2 (pat) at k=256; then fp16 LN (warp-per-row)
    gemm_h<128,4,false><<<dim3(Hdim/128, GY), 256>>>(
        cur_h, Hdim, pat, Hdim, Hdim,
        fusw_h, 2*Hdim,
        fused, Hdim, 2*Hdim, fus_b, nullptr, 0, nullptr, 0);
    ln_h_kernel<<<M/8, 256>>>(fused, fus_g, fus_bb);

    // logits = fused @ head_w^T + head_b, scattered to [b][c][t][v]
    gemm_h<128,5,false><<<dim3((Cch*Vsz)/128, GY), 256>>>(
        fused, Hdim, fused, Hdim, 1<<30,
        headw_h, Hdim,
        out, 0, Hdim, head_b, nullptr, 0, nullptr, 0);
}